// round 2
// baseline (speedup 1.0000x reference)
#include <cuda_runtime.h>
#include <cstdint>

// Problem shapes (fixed)
constexpr int kT = 256;
constexpr int kB = 128;
constexpr int kD = 1024;
constexpr int kH = 1024;
constexpr int kN3 = 3072;                 // 3 gates (f,i,g), o-gate skipped
constexpr long kTBH = (long)kT * kB * kH; // 33554432
constexpr int kBH = kB * kH;              // 131072

// ---------------- device scratch (static globals; no allocation) -------------
__device__ float g_Wx[kD * kN3];               // [k][n3], tf32-rounded, 12.6 MB
__device__ float g_Wh[kH * kN3];               // [k][n3], tf32-rounded, 12.6 MB
__device__ float g_b3[kN3];
__device__ float g_zx[(size_t)kT * kB * kN3];  // x-path preactivations, 402 MB
__device__ float g_hex[2][kBH];                // exact fp32 state (double buffered)
__device__ float g_hro[2][kBH];                // tf32-rounded state for GEMM operand

// ---------------- helpers ----------------------------------------------------
__device__ __forceinline__ float rna_tf32(float x) {
    uint32_t u;
    asm("cvt.rna.tf32.f32 %0, %1;" : "=r"(u) : "f"(x));
    return __uint_as_float(u);
}

__device__ __forceinline__ uint32_t sptr(const void* p) {
    return (uint32_t)__cvta_generic_to_shared(p);
}

__device__ __forceinline__ void cp_async16(uint32_t s, const void* g) {
    asm volatile("cp.async.cg.shared.global [%0], [%1], 16;\n" ::"r"(s), "l"(g));
}
__device__ __forceinline__ void cp_commit() { asm volatile("cp.async.commit_group;\n"); }
template <int N>
__device__ __forceinline__ void cp_wait() { asm volatile("cp.async.wait_group %0;\n" ::"n"(N)); }

// mma.sync m16n8k8 tf32: A row-major 16x8, B col-major-fragment 8x8, C fp32
__device__ __forceinline__ void mma_tf32(float (&c)[4], const uint32_t (&a)[4],
                                         const uint32_t (&b)[2]) {
    asm volatile(
        "mma.sync.aligned.m16n8k8.row.col.f32.tf32.tf32.f32 "
        "{%0,%1,%2,%3}, {%4,%5,%6,%7}, {%8,%9}, {%0,%1,%2,%3};\n"
        : "+f"(c[0]), "+f"(c[1]), "+f"(c[2]), "+f"(c[3])
        : "r"(a[0]), "r"(a[1]), "r"(a[2]), "r"(a[3]), "r"(b[0]), "r"(b[1]));
}

// ---------------- prep: pack weights (tf32-round), bias, zero state ----------
__global__ void prep_kernel(const float* __restrict__ Wf, const float* __restrict__ bf,
                            const float* __restrict__ Wi, const float* __restrict__ bi,
                            const float* __restrict__ Wg, const float* __restrict__ bg) {
    int idx = blockIdx.x * blockDim.x + threadIdx.x;
    int stride = gridDim.x * blockDim.x;
    for (int p = idx; p < kD * kN3; p += stride) {
        int k = p / kN3, n = p % kN3;
        int gate = n >> 10, j = n & 1023;
        const float* Ws = (gate == 0) ? Wf : (gate == 1) ? Wi : Wg;
        g_Wx[p] = rna_tf32(Ws[k * kH + j]);
        g_Wh[p] = rna_tf32(Ws[(kD + k) * kH + j]);
    }
    for (int n = idx; n < kN3; n += stride) {
        int gate = n >> 10, j = n & 1023;
        const float* bs = (gate == 0) ? bf : (gate == 1) ? bi : bg;
        g_b3[n] = bs[j];
    }
    for (int p = idx; p < kBH; p += stride) {
        g_hex[0][p] = 0.f;
        g_hro[0][p] = 0.f;
    }
}

// ---------------- phase 1: Z_x = X @ W_x + b  (M=32768, N=3072, K=1024) ------
constexpr int ZBM = 128, ZBN = 128, ZBK = 32;
constexpr int ZAS = ZBK + 4;   // 36, padded stride for A smem [128][36]
constexpr int ZBS = ZBN + 4;   // 132, padded stride for B smem [32][132]
constexpr int ZSMEM = 2 * (ZBM * ZAS + ZBK * ZBS) * (int)sizeof(float);  // 70656 B

__global__ void __launch_bounds__(256, 1) zx_gemm(const float* __restrict__ X) {
    extern __shared__ float zsm[];
    float* As = zsm;                       // [2][128][36]
    float* Bs = zsm + 2 * ZBM * ZAS;       // [2][32][132]

    const int tid = threadIdx.x;
    const int m0 = blockIdx.y * ZBM;
    const int n0 = blockIdx.x * ZBN;
    const int warp = tid >> 5, lane = tid & 31;
    const int wm = warp & 3, wn = warp >> 2;   // 4x2 warp grid (32M x 64N tiles)
    const int g4 = lane >> 2, t4 = lane & 3;

    float acc[2][8][4];
#pragma unroll
    for (int a = 0; a < 2; a++)
#pragma unroll
        for (int b = 0; b < 8; b++)
#pragma unroll
            for (int e = 0; e < 4; e++) acc[a][b][e] = 0.f;

    const uint32_t a_base = sptr(As);
    const uint32_t b_base = sptr(Bs);

    auto load_tiles = [&](int buf, int kb) {
        // A: 128 rows x 32 floats = 1024 x 16B chunks, 4 per thread
#pragma unroll
        for (int i = 0; i < 4; i++) {
            int q = tid + i * 256;
            int r = q >> 3, c4 = (q & 7) * 4;
            const float* gp = X + (size_t)(m0 + r) * kD + kb * ZBK + c4;
            cp_async16(a_base + ((buf * ZBM + r) * ZAS + c4) * 4, gp);
        }
        // B: 32 rows x 128 floats = 1024 x 16B chunks, 4 per thread
#pragma unroll
        for (int i = 0; i < 4; i++) {
            int q = tid + i * 256;
            int r = q >> 5, c4 = (q & 31) * 4;
            const float* gp = g_Wx + (size_t)(kb * ZBK + r) * kN3 + n0 + c4;
            cp_async16(b_base + ((buf * ZBK + r) * ZBS + c4) * 4, gp);
        }
        cp_commit();
    };

    constexpr int nK = kD / ZBK;  // 32
    load_tiles(0, 0);
    for (int kb = 0; kb < nK; kb++) {
        int buf = kb & 1;
        if (kb + 1 < nK) {
            load_tiles(buf ^ 1, kb + 1);
            cp_wait<1>();
        } else {
            cp_wait<0>();
        }
        __syncthreads();

        const float* Ab = As + buf * ZBM * ZAS;
        const float* Bb = Bs + buf * ZBK * ZBS;
#pragma unroll
        for (int ks = 0; ks < ZBK / 8; ks++) {
            const int k0 = ks * 8;
            uint32_t af[2][4], bf2[8][2];
#pragma unroll
            for (int mt = 0; mt < 2; mt++) {
                int row = wm * 32 + mt * 16 + g4;
                af[mt][0] = __float_as_uint(Ab[row * ZAS + k0 + t4]);
                af[mt][1] = __float_as_uint(Ab[(row + 8) * ZAS + k0 + t4]);
                af[mt][2] = __float_as_uint(Ab[row * ZAS + k0 + t4 + 4]);
                af[mt][3] = __float_as_uint(Ab[(row + 8) * ZAS + k0 + t4 + 4]);
            }
#pragma unroll
            for (int nt = 0; nt < 8; nt++) {
                int col = wn * 64 + nt * 8 + g4;
                bf2[nt][0] = __float_as_uint(Bb[(k0 + t4) * ZBS + col]);
                bf2[nt][1] = __float_as_uint(Bb[(k0 + t4 + 4) * ZBS + col]);
            }
#pragma unroll
            for (int mt = 0; mt < 2; mt++)
#pragma unroll
                for (int nt = 0; nt < 8; nt++) mma_tf32(acc[mt][nt], af[mt], bf2[nt]);
        }
        __syncthreads();
    }

    // epilogue: += bias, store to g_zx
#pragma unroll
    for (int mt = 0; mt < 2; mt++) {
#pragma unroll
        for (int nt = 0; nt < 8; nt++) {
#pragma unroll
            for (int e = 0; e < 4; e++) {
                int row = m0 + wm * 32 + mt * 16 + g4 + ((e >= 2) ? 8 : 0);
                int col = n0 + wn * 64 + nt * 8 + 2 * t4 + (e & 1);
                g_zx[(size_t)row * kN3 + col] = acc[mt][nt][e] + g_b3[col];
            }
        }
    }
}

// ---------------- per-step: z_h = h @ W_h slice; gates; state update ---------
// Grid: 128 CTAs = 2 M-splits x 64 j-blocks (16 h-columns each). 128 threads.
// Each CTA computes columns {j, 1024+j, 2048+j} for its j-slice over full K,
// so gate fusion needs no inter-CTA sync; step ordering comes from launches.
constexpr int SBK = 32;
constexpr int SAS = SBK + 4;   // 36
constexpr int SBS = 48 + 4;    // 52

__global__ void __launch_bounds__(128, 2) lstm_step(int t, float* __restrict__ out) {
    __shared__ float sm[2 * 64 * SAS + 2 * SBK * SBS];
    float* As = sm;                      // [2][64][36]
    float* Bs = sm + 2 * 64 * SAS;       // [2][32][52]

    const int tid = threadIdx.x;
    const int warp = tid >> 5, lane = tid & 31;
    const int g4 = lane >> 2, t4 = lane & 3;
    const int ms = blockIdx.x & 1, jb = blockIdx.x >> 1;
    const int m0 = ms * 64;
    const int j0 = jb * 16;
    const int rp = t & 1;
    const float* __restrict__ hin = g_hro[rp];

    float acc[6][4];
#pragma unroll
    for (int a = 0; a < 6; a++)
#pragma unroll
        for (int e = 0; e < 4; e++) acc[a][e] = 0.f;

    const uint32_t a_base = sptr(As);
    const uint32_t b_base = sptr(Bs);

    auto load_tiles = [&](int buf, int kb) {
        // A: 64 rows x 32 floats = 512 x 16B chunks, 4 per thread
#pragma unroll
        for (int i = 0; i < 4; i++) {
            int q = tid + i * 128;
            int r = q >> 3, c4 = (q & 7) * 4;
            const float* gp = hin + (size_t)(m0 + r) * kH + kb * SBK + c4;
            cp_async16(a_base + ((buf * 64 + r) * SAS + c4) * 4, gp);
        }
        // B: 32 rows x 3 gate-blocks x 16 floats = 384 x 16B chunks, 3 per thread
#pragma unroll
        for (int i = 0; i < 3; i++) {
            int q = tid + i * 128;
            int r = q / 12, cc = q % 12;
            int gate = cc >> 2, c4 = (cc & 3) * 4;
            const float* gp = g_Wh + (size_t)(kb * SBK + r) * kN3 + gate * 1024 + j0 + c4;
            cp_async16(b_base + ((buf * SBK + r) * SBS + gate * 16 + c4) * 4, gp);
        }
        cp_commit();
    };

    constexpr int nK = kH / SBK;  // 32
    load_tiles(0, 0);
    for (int kb = 0; kb < nK; kb++) {
        int buf = kb & 1;
        if (kb + 1 < nK) {
            load_tiles(buf ^ 1, kb + 1);
            cp_wait<1>();
        } else {
            cp_wait<0>();
        }
        __syncthreads();

        const float* Ab = As + buf * 64 * SAS;
        const float* Bb = Bs + buf * SBK * SBS;
#pragma unroll
        for (int ks = 0; ks < SBK / 8; ks++) {
            const int k0 = ks * 8;
            uint32_t af[4], bf2[6][2];
            {
                int row = warp * 16 + g4;
                af[0] = __float_as_uint(Ab[row * SAS + k0 + t4]);
                af[1] = __float_as_uint(Ab[(row + 8) * SAS + k0 + t4]);
                af[2] = __float_as_uint(Ab[row * SAS + k0 + t4 + 4]);
                af[3] = __float_as_uint(Ab[(row + 8) * SAS + k0 + t4 + 4]);
            }
#pragma unroll
            for (int nt = 0; nt < 6; nt++) {
                int col = nt * 8 + g4;
                bf2[nt][0] = __float_as_uint(Bb[(k0 + t4) * SBS + col]);
                bf2[nt][1] = __float_as_uint(Bb[(k0 + t4 + 4) * SBS + col]);
            }
#pragma unroll
            for (int nt = 0; nt < 6; nt++) mma_tf32(acc[nt], af, bf2[nt]);
        }
        __syncthreads();
    }

    // finalize: z = acc + zx (zx already has bias); gates; write out + new state
#pragma unroll
    for (int nt = 0; nt < 2; nt++) {
#pragma unroll
        for (int e = 0; e < 4; e++) {
            const int q = e & 1;
            const int half = e >> 1;
            const int j = j0 + nt * 8 + 2 * t4 + q;
            const int brow = m0 + warp * 16 + g4 + half * 8;
            const size_t zb = (size_t)(t * kB + brow) * kN3;
            const float zf = acc[nt][e] + g_zx[zb + j];
            const float zi = acc[nt + 2][e] + g_zx[zb + 1024 + j];
            const float zg = acc[nt + 4][e] + g_zx[zb + 2048 + j];
            const float c_old = g_hex[rp][brow * kH + j];
            const float f = 1.f / (1.f + __expf(-zf));
            const float i = 1.f / (1.f + __expf(-zi));
            const float g = tanhf(zg);
            const float nv = f * c_old + i * g;
            out[(size_t)(t * kB + brow) * kH + j] = nv;
            g_hex[rp ^ 1][brow * kH + j] = nv;
            g_hro[rp ^ 1][brow * kH + j] = rna_tf32(nv);
            if (t == kT - 1) {
                out[kTBH + (size_t)brow * kH + j] = nv;          // h
                out[kTBH + kBH + (size_t)brow * kH + j] = nv;    // c (== h)
            }
        }
    }
}

// ---------------- launch -----------------------------------------------------
extern "C" void kernel_launch(void* const* d_in, const int* in_sizes, int n_in,
                              void* d_out, int out_size) {
    (void)in_sizes; (void)n_in; (void)out_size;
    const float* X  = (const float*)d_in[0];
    const float* Wf = (const float*)d_in[1];
    const float* bf = (const float*)d_in[2];
    const float* Wi = (const float*)d_in[3];
    const float* bi = (const float*)d_in[4];
    const float* Wg = (const float*)d_in[5];
    const float* bg = (const float*)d_in[6];
    // d_in[7], d_in[8] = W_o, b_o: unused by the reference's output path.
    float* out = (float*)d_out;

    cudaFuncSetAttribute(zx_gemm, cudaFuncAttributeMaxDynamicSharedMemorySize, ZSMEM);

    prep_kernel<<<512, 256>>>(Wf, bf, Wi, bi, Wg, bg);
    zx_gemm<<<dim3(kN3 / ZBN, kT * kB / ZBM), 256, ZSMEM>>>(X);
    for (int t = 0; t < kT; t++) {
        lstm_step<<<128, 128>>>(t, out);
    }
}

// round 7
// speedup vs baseline: 1.0390x; 1.0390x over previous
#include <cuda_runtime.h>
#include <cstdint>

// Problem shapes (fixed)
constexpr int kT = 256;
constexpr int kB = 128;
constexpr int kD = 1024;
constexpr int kH = 1024;
constexpr int kN3 = 3072;                 // 3 gates (f,i,g), o-gate skipped
constexpr long kTBH = (long)kT * kB * kH; // 33554432
constexpr int kBH = kB * kH;              // 131072

// ---------------- device scratch (static globals; no allocation) -------------
__device__ float g_Wx[kD * kN3];               // [k][n3], tf32-rounded
__device__ float g_Wh[kH * kN3];               // [k][n3], tf32-rounded
__device__ float g_b3[kN3];
__device__ float g_zx[(size_t)kT * kB * kN3];  // x-path preactivations, 402 MB
__device__ float g_hex[2][kBH];                // exact fp32 state (double buffered)
__device__ float g_hro[2][kBH];                // tf32-rounded state (GEMM operand)
__device__ unsigned g_bar;                     // grid barrier counter

// ---------------- helpers ----------------------------------------------------
__device__ __forceinline__ float rna_tf32(float x) {
    uint32_t u;
    asm("cvt.rna.tf32.f32 %0, %1;" : "=r"(u) : "f"(x));
    return __uint_as_float(u);
}

__device__ __forceinline__ uint32_t sptr(const void* p) {
    return (uint32_t)__cvta_generic_to_shared(p);
}

__device__ __forceinline__ void cp_async16(uint32_t s, const void* g) {
    asm volatile("cp.async.cg.shared.global [%0], [%1], 16;\n" ::"r"(s), "l"(g));
}
__device__ __forceinline__ void cp_commit() { asm volatile("cp.async.commit_group;\n"); }
template <int N>
__device__ __forceinline__ void cp_wait() { asm volatile("cp.async.wait_group %0;\n" ::"n"(N)); }

// mma.sync m16n8k8 tf32: A row-major 16x8, B col-major-fragment 8x8, C fp32
__device__ __forceinline__ void mma_tf32(float (&c)[4], const uint32_t (&a)[4],
                                         const uint32_t (&b)[2]) {
    asm volatile(
        "mma.sync.aligned.m16n8k8.row.col.f32.tf32.tf32.f32 "
        "{%0,%1,%2,%3}, {%4,%5,%6,%7}, {%8,%9}, {%0,%1,%2,%3};\n"
        : "+f"(c[0]), "+f"(c[1]), "+f"(c[2]), "+f"(c[3])
        : "r"(a[0]), "r"(a[1]), "r"(a[2]), "r"(a[3]), "r"(b[0]), "r"(b[1]));
}

// ---------------- prep: pack weights (tf32-round), bias, zero state ----------
__global__ void prep_kernel(const float* __restrict__ Wf, const float* __restrict__ bf,
                            const float* __restrict__ Wi, const float* __restrict__ bi,
                            const float* __restrict__ Wg, const float* __restrict__ bg) {
    int idx = blockIdx.x * blockDim.x + threadIdx.x;
    int stride = gridDim.x * blockDim.x;
    if (idx == 0) g_bar = 0u;
    for (int p = idx; p < kD * kN3; p += stride) {
        int k = p / kN3, n = p % kN3;
        int gate = n >> 10, j = n & 1023;
        const float* Ws = (gate == 0) ? Wf : (gate == 1) ? Wi : Wg;
        g_Wx[p] = rna_tf32(Ws[k * kH + j]);
        g_Wh[p] = rna_tf32(Ws[(kD + k) * kH + j]);
    }
    for (int n = idx; n < kN3; n += stride) {
        int gate = n >> 10, j = n & 1023;
        const float* bs = (gate == 0) ? bf : (gate == 1) ? bi : bg;
        g_b3[n] = bs[j];
    }
    for (int p = idx; p < kBH; p += stride) {
        g_hex[0][p] = 0.f;
        g_hro[0][p] = 0.f;
    }
}

// ---------------- phase 1: Z_x = X @ W_x + b  (M=32768, N=3072, K=1024) ------
constexpr int ZBM = 128, ZBN = 128, ZBK = 32;
constexpr int ZAS = ZBK + 4;   // 36
constexpr int ZBS = ZBN + 4;   // 132
constexpr int ZSMEM = 2 * (ZBM * ZAS + ZBK * ZBS) * (int)sizeof(float);  // 70656 B

__global__ void __launch_bounds__(256, 1) zx_gemm(const float* __restrict__ X) {
    extern __shared__ float zsm[];
    float* As = zsm;                       // [2][128][36]
    float* Bs = zsm + 2 * ZBM * ZAS;       // [2][32][132]

    const int tid = threadIdx.x;
    const int m0 = blockIdx.y * ZBM;
    const int n0 = blockIdx.x * ZBN;
    const int warp = tid >> 5, lane = tid & 31;
    const int wm = warp & 3, wn = warp >> 2;   // 4x2 warp grid
    const int g4 = lane >> 2, t4 = lane & 3;

    float acc[2][8][4];
#pragma unroll
    for (int a = 0; a < 2; a++)
#pragma unroll
        for (int b = 0; b < 8; b++)
#pragma unroll
            for (int e = 0; e < 4; e++) acc[a][b][e] = 0.f;

    const uint32_t a_base = sptr(As);
    const uint32_t b_base = sptr(Bs);

    auto load_tiles = [&](int buf, int kb) {
#pragma unroll
        for (int i = 0; i < 4; i++) {
            int q = tid + i * 256;
            int r = q >> 3, c4 = (q & 7) * 4;
            const float* gp = X + (size_t)(m0 + r) * kD + kb * ZBK + c4;
            cp_async16(a_base + ((buf * ZBM + r) * ZAS + c4) * 4, gp);
        }
#pragma unroll
        for (int i = 0; i < 4; i++) {
            int q = tid + i * 256;
            int r = q >> 5, c4 = (q & 31) * 4;
            const float* gp = g_Wx + (size_t)(kb * ZBK + r) * kN3 + n0 + c4;
            cp_async16(b_base + ((buf * ZBK + r) * ZBS + c4) * 4, gp);
        }
        cp_commit();
    };

    constexpr int nK = kD / ZBK;  // 32
    load_tiles(0, 0);
    for (int kb = 0; kb < nK; kb++) {
        int buf = kb & 1;
        if (kb + 1 < nK) {
            load_tiles(buf ^ 1, kb + 1);
            cp_wait<1>();
        } else {
            cp_wait<0>();
        }
        __syncthreads();

        const float* Ab = As + buf * ZBM * ZAS;
        const float* Bb = Bs + buf * ZBK * ZBS;
#pragma unroll
        for (int ks = 0; ks < ZBK / 8; ks++) {
            const int k0 = ks * 8;
            uint32_t af[2][4], bf2[8][2];
#pragma unroll
            for (int mt = 0; mt < 2; mt++) {
                int row = wm * 32 + mt * 16 + g4;
                af[mt][0] = __float_as_uint(Ab[row * ZAS + k0 + t4]);
                af[mt][1] = __float_as_uint(Ab[(row + 8) * ZAS + k0 + t4]);
                af[mt][2] = __float_as_uint(Ab[row * ZAS + k0 + t4 + 4]);
                af[mt][3] = __float_as_uint(Ab[(row + 8) * ZAS + k0 + t4 + 4]);
            }
#pragma unroll
            for (int nt = 0; nt < 8; nt++) {
                int col = wn * 64 + nt * 8 + g4;
                bf2[nt][0] = __float_as_uint(Bb[(k0 + t4) * ZBS + col]);
                bf2[nt][1] = __float_as_uint(Bb[(k0 + t4 + 4) * ZBS + col]);
            }
#pragma unroll
            for (int mt = 0; mt < 2; mt++)
#pragma unroll
                for (int nt = 0; nt < 8; nt++) mma_tf32(acc[mt][nt], af[mt], bf2[nt]);
        }
        __syncthreads();
    }

#pragma unroll
    for (int mt = 0; mt < 2; mt++) {
#pragma unroll
        for (int nt = 0; nt < 8; nt++) {
#pragma unroll
            for (int e = 0; e < 4; e++) {
                int row = m0 + wm * 32 + mt * 16 + g4 + ((e >= 2) ? 8 : 0);
                int col = n0 + wn * 64 + nt * 8 + 2 * t4 + (e & 1);
                g_zx[(size_t)row * kN3 + col] = acc[mt][nt][e] + g_b3[col];
            }
        }
    }
}

// ---------------- phase 2: PERSISTENT recurrence kernel ----------------------
// Grid: 128 CTAs = 2 M-splits (64 rows) x 64 j-blocks (16 h-cols => 48 gate-cols).
// W_h slice lives in SMEM for the whole kernel, pre-arranged in mma B-fragment
// layout: [ksg(128)][gate(3)][half(2)][lane(32)][2] floats = 192 KB exactly.
// Steps separated by a release/acquire grid barrier; h state double-buffered.
constexpr int PGRID = 128;
constexpr int PAS = 36;                        // A smem row stride (conflict-free)
constexpr int SM_BFRAG = 1024 * 48;            // 49152 floats = 192 KB
constexpr int SM_A = 2 * 64 * PAS;             // 4608 floats = 18 KB
constexpr int PSMEM = (SM_BFRAG + SM_A) * (int)sizeof(float);  // 215040 B

__global__ void __launch_bounds__(128, 1) lstm_persist(float* __restrict__ out) {
    extern __shared__ float sm[];
    float* Bf = sm;                 // resident weight fragments
    float* As = sm + SM_BFRAG;      // [2][64][36] h staging

    const int tid = threadIdx.x;
    const int warp = tid >> 5, lane = tid & 31;
    const int g4 = lane >> 2, t4 = lane & 3;
    const int wm = warp & 1, wn = warp >> 1;   // 2M x 2N warp grid (32r x 24c)
    const int ms = blockIdx.x & 1, jb = blockIdx.x >> 1;
    const int m0 = ms * 64;
    const int j0 = jb * 16;

    // ---- one-time: load W_h slice into fragment-layout SMEM ----
    for (int f = warp; f < 768; f += 4) {       // 768 = 128 ksg * 3 gates * 2 halves
        int ksg = f / 6, rem = f % 6, gate = rem >> 1, hh = rem & 1;
        int colg = gate * 1024 + j0 + hh * 8 + g4;
        float v0 = g_Wh[(size_t)(ksg * 8 + t4) * kN3 + colg];
        float v1 = g_Wh[(size_t)(ksg * 8 + t4 + 4) * kN3 + colg];
        *reinterpret_cast<float2*>(Bf + (size_t)(f * 32 + lane) * 2) = make_float2(v0, v1);
    }
    __syncthreads();

    const uint32_t a_base = sptr(As);

    for (int t = 0; t < kT; t++) {
        const int rp = t & 1;
        const float* __restrict__ hin = g_hro[rp];

        float acc[2][3][4];
#pragma unroll
        for (int a = 0; a < 2; a++)
#pragma unroll
            for (int b = 0; b < 3; b++)
#pragma unroll
                for (int e = 0; e < 4; e++) acc[a][b][e] = 0.f;

        auto loadA = [&](int buf, int kb) {
#pragma unroll
            for (int i = 0; i < 4; i++) {
                int q = tid + i * 128;
                int r = q >> 3, c4 = (q & 7) * 4;
                cp_async16(a_base + ((buf * 64 + r) * PAS + c4) * 4,
                           hin + (size_t)(m0 + r) * kH + kb * 32 + c4);
            }
            cp_commit();
        };

        loadA(0, 0);
        for (int kb = 0; kb < 32; kb++) {
            int buf = kb & 1;
            if (kb + 1 < 32) {
                loadA(buf ^ 1, kb + 1);
                cp_wait<1>();
            } else {
                cp_wait<0>();
            }
            __syncthreads();

            const float* Ab = As + buf * 64 * PAS;
#pragma unroll
            for (int ks = 0; ks < 4; ks++) {
                const int k0 = ks * 8;
                const int ksg = kb * 4 + ks;
                uint32_t af[2][4];
#pragma unroll
                for (int mt = 0; mt < 2; mt++) {
                    int row = wm * 32 + mt * 16 + g4;
                    af[mt][0] = __float_as_uint(Ab[row * PAS + k0 + t4]);
                    af[mt][1] = __float_as_uint(Ab[(row + 8) * PAS + k0 + t4]);
                    af[mt][2] = __float_as_uint(Ab[row * PAS + k0 + t4 + 4]);
                    af[mt][3] = __float_as_uint(Ab[(row + 8) * PAS + k0 + t4 + 4]);
                }
#pragma unroll
                for (int g = 0; g < 3; g++) {
                    const float2 bv = *reinterpret_cast<const float2*>(
                        Bf + (size_t)((((ksg * 3 + g) * 2 + wn) * 32 + lane)) * 2);
                    uint32_t bfr[2] = {__float_as_uint(bv.x), __float_as_uint(bv.y)};
                    mma_tf32(acc[0][g], af[0], bfr);
                    mma_tf32(acc[1][g], af[1], bfr);
                }
            }
            __syncthreads();
        }

        // ---- gates + state update ----
        const size_t trow = (size_t)t * kB;
#pragma unroll
        for (int mt = 0; mt < 2; mt++) {
#pragma unroll
            for (int e = 0; e < 4; e++) {
                const int brow = m0 + wm * 32 + mt * 16 + g4 + ((e >= 2) ? 8 : 0);
                const int j = j0 + wn * 8 + 2 * t4 + (e & 1);
                const size_t zb = (trow + brow) * (size_t)kN3;
                const float zf = acc[mt][0][e] + g_zx[zb + j];
                const float zi = acc[mt][1][e] + g_zx[zb + 1024 + j];
                const float zg = acc[mt][2][e] + g_zx[zb + 2048 + j];
                const float c_old = g_hex[rp][brow * kH + j];
                const float fg = 1.f / (1.f + __expf(-zf));
                const float ig = 1.f / (1.f + __expf(-zi));
                const float gg = tanhf(zg);
                const float nv = fg * c_old + ig * gg;
                out[(trow + brow) * (size_t)kH + j] = nv;
                g_hex[rp ^ 1][brow * kH + j] = nv;
                g_hro[rp ^ 1][brow * kH + j] = rna_tf32(nv);
                if (t == kT - 1) {
                    out[kTBH + (size_t)brow * kH + j] = nv;        // h
                    out[kTBH + kBH + (size_t)brow * kH + j] = nv;  // c (== h)
                }
            }
        }

        // ---- grid barrier: release our writes, wait for all CTAs ----
        __threadfence();
        __syncthreads();
        if (tid == 0) {
            atomicAdd(&g_bar, 1u);
            const unsigned target = (unsigned)PGRID * (unsigned)(t + 1);
            unsigned v;
            do {
                asm volatile("ld.global.acquire.gpu.u32 %0, [%1];" : "=r"(v) : "l"(&g_bar));
            } while (v < target);
        }
        __syncthreads();
    }
}

// ---------------- launch -----------------------------------------------------
extern "C" void kernel_launch(void* const* d_in, const int* in_sizes, int n_in,
                              void* d_out, int out_size) {
    (void)in_sizes; (void)n_in; (void)out_size;
    const float* X  = (const float*)d_in[0];
    const float* Wf = (const float*)d_in[1];
    const float* bf = (const float*)d_in[2];
    const float* Wi = (const float*)d_in[3];
    const float* bi = (const float*)d_in[4];
    const float* Wg = (const float*)d_in[5];
    const float* bg = (const float*)d_in[6];
    float* out = (float*)d_out;

    cudaFuncSetAttribute(zx_gemm, cudaFuncAttributeMaxDynamicSharedMemorySize, ZSMEM);
    cudaFuncSetAttribute(lstm_persist, cudaFuncAttributeMaxDynamicSharedMemorySize, PSMEM);

    prep_kernel<<<512, 256>>>(Wf, bf, Wi, bi, Wg, bg);
    zx_gemm<<<dim3(kN3 / ZBN, kT * kB / ZBM), 256, ZSMEM>>>(X);
    lstm_persist<<<PGRID, 128, PSMEM>>>(out);
}